// round 7
// baseline (speedup 1.0000x reference)
#include <cuda_runtime.h>
#include <math.h>

// Problem constants (fixed by the reference: B=8192, V=8, J=32)
constexpr int BB = 8192;
constexpr int VV = 8;
constexpr int JJ = 32;
constexpr int PAIRS = BB * VV;                        // 65536 (b,v) problems
constexpr int WARPS_PER_BLOCK = 8;
constexpr int PAIRS_PER_WARP = 8;                     // 4-lane segments; 1 warp = 1 batch
constexpr int PAIRS_PER_BLOCK = WARPS_PER_BLOCK * PAIRS_PER_WARP;  // 64
constexpr int NBLOCKS = PAIRS / PAIRS_PER_BLOCK;      // 1024
constexpr float SCALE_KPS = 0.1f;
constexpr float THRESHOLD = 100.0f;
constexpr float ALPHA = 0.1f;
constexpr float T_BETA = 63.095734448019324f;         // 100^0.9
constexpr double FIX = 262144.0;                      // 2^18 fixed-point scale

__device__ unsigned long long g_accum = 0ull;         // fixed-point grid sum
__device__ unsigned int g_ticket = 0u;                // completion counter

struct Acc { float pn2, in2, ls; };

__device__ __forceinline__ void do_joint(
    float X, float Y, float Z, float ix, float iy,
    const float4& c0, const float4& c1, const float4& c2,
    const float* __restrict__ kk, Acc& a)
{
    const float cx = c0.x * X + c0.y * Y + c0.z * Z + c0.w;
    const float cy = c1.x * X + c1.y * Y + c1.z * Z + c1.w;
    const float cz = c2.x * X + c2.y * Y + c2.z * Z + c2.w;
    const float px = kk[0] * cx + kk[1] * cy + kk[2] * cz;
    const float py = kk[3] * cx + kk[4] * cy + kk[5] * cz;
    const float pz = kk[6] * cx + kk[7] * cy + kk[8] * cz;
    const float iz = __frcp_rn(pz);
    const float u = px * iz, w = py * iz;
    a.pn2 += u * u + w * w;
    a.in2 += ix * ix + iy * iy;
    float d0 = (u - ix) * SCALE_KPS; d0 = d0 * d0;
    float d1 = (w - iy) * SCALE_KPS; d1 = d1 * d1;
    if (d0 > THRESHOLD) d0 = __powf(d0, ALPHA) * T_BETA;
    if (d1 > THRESHOLD) d1 = __powf(d1, ALPHA) * T_BETA;
    a.ls += d0 + d1;
}

__global__ __launch_bounds__(WARPS_PER_BLOCK * 32)
void qpl_fused(const float* __restrict__ Kmat,
               const float* __restrict__ cam,
               const float* __restrict__ kps,
               const float* __restrict__ init,
               float* __restrict__ out) {
    const int t = threadIdx.x;
    const int warp = t >> 5;
    const int lane = t & 31;
    const int grp = lane >> 2;      // which of 8 pairs (views) in this warp
    const int sub = lane & 3;       // lane in 4-lane group; handles joints 8*sub..8*sub+7
    const int b = blockIdx.x * WARPS_PER_BLOCK + warp;   // one warp = one batch
    const int pair = b * VV + grp;

    // ---- loads: 16B-aligned vectors / group-uniform broadcast ----
    // init: joints 8sub..8sub+7 -> 4 float4
    const float4* ikp = reinterpret_cast<const float4*>(init) + (size_t)pair * 16 + sub * 4;
    const float4 i0 = ikp[0], i1 = ikp[1], i2 = ikp[2], i3 = ikp[3];
    // kps: 24 floats (8 joints), 96B-aligned -> 6 float4 (warp-broadcast: same b)
    const float4* kp4 = reinterpret_cast<const float4*>(kps + (size_t)b * (JJ * 3) + sub * 24);
    const float4 r0 = kp4[0], r1 = kp4[1], r2 = kp4[2];
    const float4 r3 = kp4[3], r4 = kp4[4], r5 = kp4[5];
    // cam rows (4-lane-group-uniform)
    const float4* C = reinterpret_cast<const float4*>(cam + (size_t)pair * 12);
    const float4 c0 = C[0], c1 = C[1], c2 = C[2];
    // K (group-uniform scalars)
    const float* Kp = Kmat + (size_t)pair * 9;
    float kk[9];
#pragma unroll
    for (int i = 0; i < 9; i++) kk[i] = Kp[i];

    Acc a = {0.0f, 0.0f, 0.0f};
    // 8 independent joint chains -> ILP hides MUFU/LDG latency
    do_joint(r0.x, r0.y, r0.z, i0.x, i0.y, c0, c1, c2, kk, a);
    do_joint(r0.w, r1.x, r1.y, i0.z, i0.w, c0, c1, c2, kk, a);
    do_joint(r1.z, r1.w, r2.x, i1.x, i1.y, c0, c1, c2, kk, a);
    do_joint(r2.y, r2.z, r2.w, i1.z, i1.w, c0, c1, c2, kk, a);
    do_joint(r3.x, r3.y, r3.z, i2.x, i2.y, c0, c1, c2, kk, a);
    do_joint(r3.w, r4.x, r4.y, i2.z, i2.w, c0, c1, c2, kk, a);
    do_joint(r4.z, r4.w, r5.x, i3.x, i3.y, c0, c1, c2, kk, a);
    do_joint(r5.y, r5.z, r5.w, i3.z, i3.w, c0, c1, c2, kk, a);

    // ---- segmented butterfly reduce within each 4-lane group ----
#pragma unroll
    for (int o = 2; o; o >>= 1) {
        a.pn2 += __shfl_xor_sync(0xFFFFFFFFu, a.pn2, o);
        a.in2 += __shfl_xor_sync(0xFFFFFFFFu, a.in2, o);
        a.ls  += __shfl_xor_sync(0xFFFFFFFFu, a.ls,  o);
    }

    __shared__ float sm[PAIRS_PER_BLOCK];
    if (sub == 0) {
        const float penal = fabsf(__fsqrt_rn(a.pn2 * __frcp_rn(a.in2)) - 1.0f);
        sm[warp * PAIRS_PER_WARP + grp] = penal * a.ls * 0.5f;
    }
    __syncthreads();

    // warp 0 reduces the 64 per-pair results
    if (warp == 0) {
        float s = sm[lane] + sm[lane + 32];
#pragma unroll
        for (int o = 16; o; o >>= 1) s += __shfl_xor_sync(0xFFFFFFFFu, s, o);
        if (lane == 0) {
            // order-invariant integer accumulation => deterministic grid sum
            const long long q = __double2ll_rn((double)s * FIX);
            atomicAdd(&g_accum, (unsigned long long)q);
            __threadfence();
            const unsigned int tk = atomicAdd(&g_ticket, 1u);
            if (tk == (unsigned int)(NBLOCKS - 1)) {
                const unsigned long long total = atomicAdd(&g_accum, 0ull);
                const double mean = ((double)(long long)total) / FIX / (double)PAIRS;
                out[0] = (float)mean;
                atomicExch(&g_accum, 0ull);
                __threadfence();
                atomicExch(&g_ticket, 0u);
            }
        }
    }
}

extern "C" void kernel_launch(void* const* d_in, const int* in_sizes, int n_in,
                              void* d_out, int out_size) {
    const float* Kmat = (const float*)d_in[0];  // [B,V,3,3]
    const float* cam  = (const float*)d_in[1];  // [B,V,3,4]
    const float* kps  = (const float*)d_in[2];  // [B,J,3]
    const float* init = (const float*)d_in[3];  // [B,V,J,2]
    float* out = (float*)d_out;

    qpl_fused<<<NBLOCKS, WARPS_PER_BLOCK * 32>>>(Kmat, cam, kps, init, out);
}

// round 8
// speedup vs baseline: 1.6213x; 1.6213x over previous
#include <cuda_runtime.h>
#include <math.h>

// Problem constants (fixed by the reference: B=8192, V=8, J=32)
constexpr int BB = 8192;
constexpr int VV = 8;
constexpr int JJ = 32;
constexpr int PAIRS = BB * VV;                        // 65536 (b,v) problems
constexpr int WARPS_PER_BLOCK = 8;
constexpr int PAIRS_PER_WARP = 4;                     // 8-lane segments (best measured config)
constexpr int PAIRS_PER_BLOCK = WARPS_PER_BLOCK * PAIRS_PER_WARP;  // 32
constexpr int NBLOCKS = PAIRS / PAIRS_PER_BLOCK;      // 2048
constexpr float SCALE_KPS = 0.1f;
constexpr float THRESHOLD = 100.0f;
constexpr float ALPHA = 0.1f;
constexpr float T_BETA = 63.095734448019324f;         // 100^0.9
constexpr double FIX = 262144.0;                      // 2^18 fixed-point scale

__device__ unsigned long long g_accum = 0ull;         // fixed-point grid sum
__device__ unsigned int g_ticket = 0u;                // completion counter

// single-MUFU approximate ops (vs IEEE __frcp_rn/__fsqrt_rn which expand to
// MUFU + Newton refinement + fixup — ~8-10 extra serial instructions each)
__device__ __forceinline__ float frcp_fast(float x) {
    float r; asm("rcp.approx.f32 %0, %1;" : "=f"(r) : "f"(x)); return r;
}
__device__ __forceinline__ float fsqrt_fast(float x) {
    float r; asm("sqrt.approx.f32 %0, %1;" : "=f"(r) : "f"(x)); return r;
}

struct Acc { float pn2, in2, ls; };

__device__ __forceinline__ void do_joint(
    float X, float Y, float Z, float ix, float iy,
    const float4& c0, const float4& c1, const float4& c2,
    const float* __restrict__ kk, Acc& a)
{
    const float cx = c0.x * X + c0.y * Y + c0.z * Z + c0.w;
    const float cy = c1.x * X + c1.y * Y + c1.z * Z + c1.w;
    const float cz = c2.x * X + c2.y * Y + c2.z * Z + c2.w;
    const float px = kk[0] * cx + kk[1] * cy + kk[2] * cz;
    const float py = kk[3] * cx + kk[4] * cy + kk[5] * cz;
    const float pz = kk[6] * cx + kk[7] * cy + kk[8] * cz;
    const float iz = frcp_fast(pz);
    const float u = px * iz, w = py * iz;
    a.pn2 += u * u + w * w;
    a.in2 += ix * ix + iy * iy;
    float d0 = (u - ix) * SCALE_KPS; d0 = d0 * d0;
    float d1 = (w - iy) * SCALE_KPS; d1 = d1 * d1;
    if (d0 > THRESHOLD) d0 = __powf(d0, ALPHA) * T_BETA;
    if (d1 > THRESHOLD) d1 = __powf(d1, ALPHA) * T_BETA;
    a.ls += d0 + d1;
}

__global__ __launch_bounds__(WARPS_PER_BLOCK * 32)
void qpl_fused(const float* __restrict__ Kmat,
               const float* __restrict__ cam,
               const float* __restrict__ kps,
               const float* __restrict__ init,
               float* __restrict__ out) {
    const int t = threadIdx.x;
    const int warp = t >> 5;
    const int lane = t & 31;
    const int grp = lane >> 3;      // which of 4 pairs in this warp
    const int sub = lane & 7;       // lane in 8-lane group; handles joints 4*sub..4*sub+3
    const int pair = blockIdx.x * PAIRS_PER_BLOCK + warp * PAIRS_PER_WARP + grp;
    const int b = pair >> 3;        // 4 consecutive pairs share one batch

    // ---- loads: 16B-aligned vectors / group-uniform broadcast ----
    const float4* ikp = reinterpret_cast<const float4*>(init) + (size_t)pair * 16 + sub * 2;
    const float4 ia = ikp[0], ib = ikp[1];
    const float4* kp4 = reinterpret_cast<const float4*>(kps + (size_t)b * (JJ * 3) + sub * 12);
    const float4 q0 = kp4[0], q1 = kp4[1], q2 = kp4[2];
    const float4* C = reinterpret_cast<const float4*>(cam + (size_t)pair * 12);
    const float4 c0 = C[0], c1 = C[1], c2 = C[2];
    const float* Kp = Kmat + (size_t)pair * 9;
    float kk[9];
#pragma unroll
    for (int i = 0; i < 9; i++) kk[i] = Kp[i];

    Acc a = {0.0f, 0.0f, 0.0f};
    // 4 independent joint chains -> ILP hides MUFU/LDG latency
    do_joint(q0.x, q0.y, q0.z, ia.x, ia.y, c0, c1, c2, kk, a);
    do_joint(q0.w, q1.x, q1.y, ia.z, ia.w, c0, c1, c2, kk, a);
    do_joint(q1.z, q1.w, q2.x, ib.x, ib.y, c0, c1, c2, kk, a);
    do_joint(q2.y, q2.z, q2.w, ib.z, ib.w, c0, c1, c2, kk, a);

    // ---- segmented butterfly reduce within each 8-lane group ----
#pragma unroll
    for (int o = 4; o; o >>= 1) {
        a.pn2 += __shfl_xor_sync(0xFFFFFFFFu, a.pn2, o);
        a.in2 += __shfl_xor_sync(0xFFFFFFFFu, a.in2, o);
        a.ls  += __shfl_xor_sync(0xFFFFFFFFu, a.ls,  o);
    }

    __shared__ float sm[PAIRS_PER_BLOCK];
    if (sub == 0) {
        const float penal = fabsf(fsqrt_fast(a.pn2 * frcp_fast(a.in2)) - 1.0f);
        sm[warp * PAIRS_PER_WARP + grp] = penal * a.ls * 0.5f;
    }
    __syncthreads();

    // warp 0 reduces the 32 per-pair results
    if (warp == 0) {
        float s = sm[lane];
#pragma unroll
        for (int o = 16; o; o >>= 1) s += __shfl_xor_sync(0xFFFFFFFFu, s, o);
        if (lane == 0) {
            // order-invariant integer accumulation => deterministic grid sum
            const long long q = __double2ll_rn((double)s * FIX);
            atomicAdd(&g_accum, (unsigned long long)q);
            __threadfence();
            const unsigned int tk = atomicAdd(&g_ticket, 1u);
            if (tk == (unsigned int)(NBLOCKS - 1)) {
                const unsigned long long total = atomicAdd(&g_accum, 0ull);
                const double mean = ((double)(long long)total) / FIX / (double)PAIRS;
                out[0] = (float)mean;
                atomicExch(&g_accum, 0ull);
                __threadfence();
                atomicExch(&g_ticket, 0u);
            }
        }
    }
}

extern "C" void kernel_launch(void* const* d_in, const int* in_sizes, int n_in,
                              void* d_out, int out_size) {
    const float* Kmat = (const float*)d_in[0];  // [B,V,3,3]
    const float* cam  = (const float*)d_in[1];  // [B,V,3,4]
    const float* kps  = (const float*)d_in[2];  // [B,J,3]
    const float* init = (const float*)d_in[3];  // [B,V,J,2]
    float* out = (float*)d_out;

    qpl_fused<<<NBLOCKS, WARPS_PER_BLOCK * 32>>>(Kmat, cam, kps, init, out);
}

// round 9
// speedup vs baseline: 2.1725x; 1.3400x over previous
#include <cuda_runtime.h>
#include <math.h>

// Problem constants (fixed by the reference: B=8192, V=8, J=32)
constexpr int BB = 8192;
constexpr int VV = 8;
constexpr int JJ = 32;
constexpr int PAIRS = BB * VV;                        // 65536 (b,v) problems
constexpr int WARPS_PER_BLOCK = 8;
constexpr int PAIRS_PER_WARP = 4;                     // 8-lane segments (best measured config)
constexpr int PAIRS_PER_BLOCK = WARPS_PER_BLOCK * PAIRS_PER_WARP;  // 32
constexpr int NBLOCKS = PAIRS / PAIRS_PER_BLOCK;      // 2048
constexpr float SCALE_KPS = 0.1f;
constexpr float THRESHOLD = 100.0f;
constexpr float ALPHA = 0.1f;
constexpr float T_BETA = 63.095734448019324f;         // 100^0.9
constexpr double FIX = 262144.0;                      // 2^18 fixed-point scale

__device__ unsigned long long g_accum = 0ull;         // fixed-point grid sum
__device__ unsigned int g_ticket = 0u;                // completion counter

// single-MUFU approximate ops
__device__ __forceinline__ float frcp_fast(float x) {
    float r; asm("rcp.approx.f32 %0, %1;" : "=f"(r) : "f"(x)); return r;
}
__device__ __forceinline__ float fsqrt_fast(float x) {
    float r; asm("sqrt.approx.f32 %0, %1;" : "=f"(r) : "f"(x)); return r;
}
// branchless x^0.1 via lg2/ex2 (we select against the plain value afterwards)
__device__ __forceinline__ float pow01_fast(float x) {
    float l; asm("lg2.approx.f32 %0, %1;" : "=f"(l) : "f"(x));
    float r; asm("ex2.approx.f32 %0, %1;" : "=f"(r) : "f"(l * ALPHA));
    return r;
}

struct Acc { float pn2, in2, ls; };

__device__ __forceinline__ void do_joint(
    float X, float Y, float Z, float ix, float iy,
    const float4& c0, const float4& c1, const float4& c2,
    const float* __restrict__ kk, Acc& a)
{
    const float cx = c0.x * X + c0.y * Y + c0.z * Z + c0.w;
    const float cy = c1.x * X + c1.y * Y + c1.z * Z + c1.w;
    const float cz = c2.x * X + c2.y * Y + c2.z * Z + c2.w;
    const float px = kk[0] * cx + kk[1] * cy + kk[2] * cz;
    const float py = kk[3] * cx + kk[4] * cy + kk[5] * cz;
    const float pz = kk[6] * cx + kk[7] * cy + kk[8] * cz;
    const float iz = frcp_fast(pz);
    const float u = px * iz, w = py * iz;
    a.pn2 += u * u + w * w;
    a.in2 += ix * ix + iy * iy;
    float d0 = (u - ix) * SCALE_KPS; d0 = d0 * d0;
    float d1 = (w - iy) * SCALE_KPS; d1 = d1 * d1;
    // branchless: compute the over-threshold value unconditionally, FSEL it in.
    // majority of lanes exceed THRESHOLD anyway, so no wasted MUFU in practice,
    // and 2 divergent branch constructs per joint disappear.
    const float o0 = pow01_fast(d0) * T_BETA;
    const float o1 = pow01_fast(d1) * T_BETA;
    d0 = (d0 > THRESHOLD) ? o0 : d0;
    d1 = (d1 > THRESHOLD) ? o1 : d1;
    a.ls += d0 + d1;
}

__global__ __launch_bounds__(WARPS_PER_BLOCK * 32, 6)   // force regs<=42 -> 48 warps/SM
void qpl_fused(const float* __restrict__ Kmat,
               const float* __restrict__ cam,
               const float* __restrict__ kps,
               const float* __restrict__ init,
               float* __restrict__ out) {
    const int t = threadIdx.x;
    const int warp = t >> 5;
    const int lane = t & 31;
    const int grp = lane >> 3;      // which of 4 pairs in this warp
    const int sub = lane & 7;       // lane in 8-lane group; handles joints 4*sub..4*sub+3
    const int pair = blockIdx.x * PAIRS_PER_BLOCK + warp * PAIRS_PER_WARP + grp;
    const int b = pair >> 3;        // 4 consecutive pairs share one batch

    // ---- loads: 16B-aligned vectors / group-uniform broadcast ----
    const float4* ikp = reinterpret_cast<const float4*>(init) + (size_t)pair * 16 + sub * 2;
    const float4 ia = ikp[0], ib = ikp[1];
    const float4* kp4 = reinterpret_cast<const float4*>(kps + (size_t)b * (JJ * 3) + sub * 12);
    const float4 q0 = kp4[0], q1 = kp4[1], q2 = kp4[2];
    const float4* C = reinterpret_cast<const float4*>(cam + (size_t)pair * 12);
    const float4 c0 = C[0], c1 = C[1], c2 = C[2];
    const float* Kp = Kmat + (size_t)pair * 9;
    float kk[9];
#pragma unroll
    for (int i = 0; i < 9; i++) kk[i] = Kp[i];

    Acc a = {0.0f, 0.0f, 0.0f};
    // 4 independent joint chains -> ILP hides MUFU/LDG latency
    do_joint(q0.x, q0.y, q0.z, ia.x, ia.y, c0, c1, c2, kk, a);
    do_joint(q0.w, q1.x, q1.y, ia.z, ia.w, c0, c1, c2, kk, a);
    do_joint(q1.z, q1.w, q2.x, ib.x, ib.y, c0, c1, c2, kk, a);
    do_joint(q2.y, q2.z, q2.w, ib.z, ib.w, c0, c1, c2, kk, a);

    // ---- segmented butterfly reduce within each 8-lane group ----
#pragma unroll
    for (int o = 4; o; o >>= 1) {
        a.pn2 += __shfl_xor_sync(0xFFFFFFFFu, a.pn2, o);
        a.in2 += __shfl_xor_sync(0xFFFFFFFFu, a.in2, o);
        a.ls  += __shfl_xor_sync(0xFFFFFFFFu, a.ls,  o);
    }

    __shared__ float sm[PAIRS_PER_BLOCK];
    if (sub == 0) {
        const float penal = fabsf(fsqrt_fast(a.pn2 * frcp_fast(a.in2)) - 1.0f);
        sm[warp * PAIRS_PER_WARP + grp] = penal * a.ls * 0.5f;
    }
    __syncthreads();

    // warp 0 reduces the 32 per-pair results
    if (warp == 0) {
        float s = sm[lane];
#pragma unroll
        for (int o = 16; o; o >>= 1) s += __shfl_xor_sync(0xFFFFFFFFu, s, o);
        if (lane == 0) {
            // order-invariant integer accumulation => deterministic grid sum
            const long long q = __double2ll_rn((double)s * FIX);
            atomicAdd(&g_accum, (unsigned long long)q);
            __threadfence();
            const unsigned int tk = atomicAdd(&g_ticket, 1u);
            if (tk == (unsigned int)(NBLOCKS - 1)) {
                const unsigned long long total = atomicAdd(&g_accum, 0ull);
                const double mean = ((double)(long long)total) / FIX / (double)PAIRS;
                out[0] = (float)mean;
                atomicExch(&g_accum, 0ull);
                __threadfence();
                atomicExch(&g_ticket, 0u);
            }
        }
    }
}

extern "C" void kernel_launch(void* const* d_in, const int* in_sizes, int n_in,
                              void* d_out, int out_size) {
    const float* Kmat = (const float*)d_in[0];  // [B,V,3,3]
    const float* cam  = (const float*)d_in[1];  // [B,V,3,4]
    const float* kps  = (const float*)d_in[2];  // [B,J,3]
    const float* init = (const float*)d_in[3];  // [B,V,J,2]
    float* out = (float*)d_out;

    qpl_fused<<<NBLOCKS, WARPS_PER_BLOCK * 32>>>(Kmat, cam, kps, init, out);
}